// round 16
// baseline (speedup 1.0000x reference)
#include <cuda_runtime.h>

typedef unsigned long long u64;

#define NBATCH 512
#define CIN 128
#define LIN 1024
#define LOUT 1020
#define TSEQ 1020

// conv output in [b][ch][pos] layout; flat slices of it are the seq rows
__device__ float g_conv[NBATCH * CIN * LOUT];
__device__ float g_xg[NBATCH * TSEQ * 128];
__device__ float g_wt[640 * 128];   // transposed conv weight: [ic*5+j][oc]

__device__ __forceinline__ u64 fma2(u64 a, u64 b, u64 c){
    u64 d; asm("fma.rn.f32x2 %0, %1, %2, %3;" : "=l"(d) : "l"(a), "l"(b), "l"(c)); return d;
}
__device__ __forceinline__ u64 pack2(float lo, float hi){
    u64 d; asm("mov.b64 %0, {%1, %2};" : "=l"(d) : "f"(lo), "f"(hi)); return d;
}
__device__ __forceinline__ float lo32(u64 v){ return __uint_as_float((unsigned)(v & 0xffffffffu)); }
__device__ __forceinline__ float hi32(u64 v){ return __uint_as_float((unsigned)(v >> 32)); }

__device__ __forceinline__ void cp16(void* dst_smem, const void* src, int srcbytes){
    unsigned d = (unsigned)__cvta_generic_to_shared(dst_smem);
    asm volatile("cp.async.ca.shared.global [%0], [%1], 16, %2;" :: "r"(d), "l"(src), "r"(srcbytes));
}
__device__ __forceinline__ void cp_commit(){ asm volatile("cp.async.commit_group;"); }

// ---------------------------------------------------------------------------
// Kernel 0: transpose conv weight w[oc][ic][j] -> g_wt[ic*5+j][oc]
// ---------------------------------------------------------------------------
__global__ void prep_kernel(const float* __restrict__ w){
    int i = blockIdx.x * 256 + threadIdx.x;
    if (i < 128 * 640) {
        int oc = i / 640, r = i - oc * 640;
        g_wt[r * 128 + oc] = w[i];
    }
}

// ---------------------------------------------------------------------------
// Kernel 1: conv1d 128->128, k=5, VALID. Implicit GEMM, f32x2 FMAs,
// cp.async double-buffered tiles of 8 input channels.
// 384 threads, thread tile 4oc x 8pos, block tile 128oc x 96pos.
// __launch_bounds__(384,2): regs capped at 85 -> 2 blocks/SM = 24 warps.
// ---------------------------------------------------------------------------
#define ICT 8
#define PTILE 96
__global__ __launch_bounds__(384, 2) void conv_kernel(
    const float* __restrict__ x, const float* __restrict__ bias)
{
    __shared__ __align__(16) float xs[2][ICT][104];   // 96 pos + 4 halo, padded
    __shared__ __align__(16) float ws[2][ICT * 5][128];

    const int b   = blockIdx.y;
    const int p0  = blockIdx.x * PTILE;
    const int tid = threadIdx.x;
    const int tx  = tid % 12;       // pos micro index (12 x 8 = 96)
    const int ty  = tid / 12;       // oc micro index  (32 x 4 = 128)
    const int oc0 = ty * 4;
    const int pp0 = tx * 8;

    u64 acc[2][8];
    #pragma unroll
    for (int m = 0; m < 2; m++)
        #pragma unroll
        for (int n = 0; n < 8; n++) acc[m][n] = 0ULL;

    const float* xb = x + (long)b * (CIN * LIN);

    auto issue_tile = [&](int it, int buf){
        int ic0 = it * ICT;
        // xs: ICT rows x 26 chunks of 16B = 208 copies
        if (tid < ICT * 26) {
            int r = tid / 26, cc = tid - r * 26;
            int gp = p0 + cc * 4;
            int nb = (LIN - gp) * 4;
            nb = nb < 0 ? 0 : (nb > 16 ? 16 : nb);
            int sg = gp > LIN - 4 ? LIN - 4 : gp;
            cp16(&xs[buf][r][cc * 4], xb + (ic0 + r) * LIN + sg, nb);
        }
        // ws: ICT*5 rows x 32 chunks of 16B = 1280 copies over 384 threads
        for (int idx = tid; idx < ICT * 5 * 32; idx += 384) {
            int k = idx >> 5, cc = idx & 31;
            cp16(&ws[buf][k][cc * 4], g_wt + (ic0 * 5 + k) * 128 + cc * 4, 16);
        }
        cp_commit();
    };

    issue_tile(0, 0);
    const int NT = CIN / ICT;   // 16
    for (int it = 0; it < NT; it++) {
        int buf = it & 1;
        if (it + 1 < NT) {
            issue_tile(it + 1, buf ^ 1);
            asm volatile("cp.async.wait_group 1;");
        } else {
            asm volatile("cp.async.wait_group 0;");
        }
        __syncthreads();

        #pragma unroll
        for (int icl = 0; icl < ICT; icl++) {
            const float4* wp = reinterpret_cast<const float4*>(&xs[buf][icl][pp0]);
            float4 v0 = wp[0], v1 = wp[1], v2 = wp[2];
            u64 pw[12];
            pw[0]=pack2(v0.x,v0.x); pw[1]=pack2(v0.y,v0.y); pw[2]=pack2(v0.z,v0.z); pw[3]=pack2(v0.w,v0.w);
            pw[4]=pack2(v1.x,v1.x); pw[5]=pack2(v1.y,v1.y); pw[6]=pack2(v1.z,v1.z); pw[7]=pack2(v1.w,v1.w);
            pw[8]=pack2(v2.x,v2.x); pw[9]=pack2(v2.y,v2.y); pw[10]=pack2(v2.z,v2.z); pw[11]=pack2(v2.w,v2.w);
            #pragma unroll
            for (int j = 0; j < 5; j++) {
                const u64* ap = reinterpret_cast<const u64*>(&ws[buf][icl * 5 + j][oc0]);
                u64 a0 = ap[0], a1 = ap[1];
                #pragma unroll
                for (int n = 0; n < 8; n++) {
                    u64 bb = pw[j + n];
                    acc[0][n] = fma2(a0, bb, acc[0][n]);
                    acc[1][n] = fma2(a1, bb, acc[1][n]);
                }
            }
        }
        __syncthreads();
    }

    float* ob = g_conv + (long)b * (CIN * LOUT);
    #pragma unroll
    for (int m = 0; m < 2; m++) {
        int oce = oc0 + 2 * m;
        float be = bias[oce], bo = bias[oce + 1];
        #pragma unroll
        for (int n = 0; n < 8; n++) {
            int p = p0 + pp0 + n;
            if (p < LOUT) {
                ob[oce * LOUT + p]       = lo32(acc[m][n]) + be;
                ob[(oce + 1) * LOUT + p] = hi32(acc[m][n]) + bo;
            }
        }
    }
}

// ---------------------------------------------------------------------------
// Kernel 2: xg1[row][g] = seq[row][:] . Wih1[g][:] + (bih1+bhh1)[g]
// seq rows are flat 128-float slices of g_conv (raw reshape semantics).
// Register-staged prefetch double buffering (single smem buffer, 2 syncs).
// ---------------------------------------------------------------------------
__global__ __launch_bounds__(256) void xg_kernel(
    const float* __restrict__ Wih1, const float* __restrict__ bih1, const float* __restrict__ bhh1)
{
    const int row0 = blockIdx.x * 128;
    const int tid  = threadIdx.x;
    const int tx   = tid & 15;
    const int ty   = tid >> 4;
    const int g0   = tx * 8;
    const int r0   = ty * 8;

    __shared__ __align__(16) float sa[16][132];
    __shared__ __align__(16) float sb[16][132];
    __shared__ float bs[128];

    if (tid < 128) bs[tid] = bih1[tid] + bhh1[tid];

    u64 acc[4][8];
    #pragma unroll
    for (int m = 0; m < 4; m++)
        #pragma unroll
        for (int n = 0; n < 8; n++) acc[m][n] = 0ULL;

    const int lr = tid >> 4;
    const int lc = tid & 15;

    float ra[8], rb[8];
    #pragma unroll
    for (int i = 0; i < 8; i++) {
        int rr = lr + i * 16;
        ra[i] = g_conv[(long)(row0 + rr) * 128 + lc];
        rb[i] = Wih1[rr * 128 + lc];
    }

    for (int t = 0; t < 8; t++) {
        #pragma unroll
        for (int i = 0; i < 8; i++) {
            int rr = lr + i * 16;
            sa[lc][rr] = ra[i];
            sb[lc][rr] = rb[i];
        }
        __syncthreads();
        if (t + 1 < 8) {
            int c0 = (t + 1) * 16;
            #pragma unroll
            for (int i = 0; i < 8; i++) {
                int rr = lr + i * 16;
                ra[i] = g_conv[(long)(row0 + rr) * 128 + c0 + lc];
                rb[i] = Wih1[rr * 128 + c0 + lc];
            }
        }
        #pragma unroll
        for (int c = 0; c < 16; c++) {
            const u64* ap = reinterpret_cast<const u64*>(&sa[c][r0]);
            u64 A0 = ap[0], A1 = ap[1], A2 = ap[2], A3 = ap[3];
            const float4* bp = reinterpret_cast<const float4*>(&sb[c][g0]);
            float4 b0 = bp[0], b1 = bp[1];
            u64 pb[8];
            pb[0]=pack2(b0.x,b0.x); pb[1]=pack2(b0.y,b0.y); pb[2]=pack2(b0.z,b0.z); pb[3]=pack2(b0.w,b0.w);
            pb[4]=pack2(b1.x,b1.x); pb[5]=pack2(b1.y,b1.y); pb[6]=pack2(b1.z,b1.z); pb[7]=pack2(b1.w,b1.w);
            #pragma unroll
            for (int n = 0; n < 8; n++) {
                acc[0][n] = fma2(A0, pb[n], acc[0][n]);
                acc[1][n] = fma2(A1, pb[n], acc[1][n]);
                acc[2][n] = fma2(A2, pb[n], acc[2][n]);
                acc[3][n] = fma2(A3, pb[n], acc[3][n]);
            }
        }
        __syncthreads();
    }
    #pragma unroll
    for (int m = 0; m < 4; m++) {
        long re = row0 + r0 + 2 * m;
        #pragma unroll
        for (int n = 0; n < 8; n++) {
            int g = g0 + n;
            g_xg[re * 128 + g]       = lo32(acc[m][n]) + bs[g];
            g_xg[(re + 1) * 128 + g] = hi32(acc[m][n]) + bs[g];
        }
    }
}

// ---------------------------------------------------------------------------
// Kernel 3: fused 3-layer LSTM scan (R12: one wave, 2 syncs/step)
// ---------------------------------------------------------------------------
__device__ __forceinline__ float sigf(float v){ return __fdividef(1.f, 1.f + __expf(-v)); }
__device__ __forceinline__ float tnh(float v){ return 1.f - __fdividef(2.f, __expf(2.f * v) + 1.f); }

__global__ __launch_bounds__(128, 4) void lstm_kernel(
    const float* __restrict__ Whh1,
    const float* __restrict__ Wih2, const float* __restrict__ Whh2,
    const float* __restrict__ bih2, const float* __restrict__ bhh2,
    const float* __restrict__ Wih3, const float* __restrict__ Whh3,
    const float* __restrict__ bih3, const float* __restrict__ bhh3,
    float* __restrict__ out)
{
    const int b   = blockIdx.x;
    const int tid = threadIdx.x;

    __shared__ __align__(16) float s_h1[32];
    __shared__ __align__(16) float s_h2[16];
    __shared__ __align__(16) float s_h3[32];
    __shared__ float s_g1[128], s_g2a[64], s_g2b[64], s_g3[128];
    __shared__ __align__(16) u64 s_wi3[8][128];

    u64 w1p[16];
    {
        const u64* W = reinterpret_cast<const u64*>(Whh1 + tid * 32);
        #pragma unroll
        for (int k = 0; k < 16; k++) w1p[k] = W[k];
    }
    u64 w2[16]; float b2 = 0.f;
    if (tid < 64) {
        const u64* W = reinterpret_cast<const u64*>(Wih2 + tid * 32);
        #pragma unroll
        for (int k = 0; k < 16; k++) w2[k] = W[k];
        b2 = bih2[tid] + bhh2[tid];
    } else {
        const u64* W = reinterpret_cast<const u64*>(Whh2 + (tid - 64) * 16);
        #pragma unroll
        for (int k = 0; k < 8; k++) w2[k] = W[k];
        #pragma unroll
        for (int k = 8; k < 16; k++) w2[k] = 0ULL;
    }
    {
        const u64* Wa = reinterpret_cast<const u64*>(Wih3 + tid * 16);
        #pragma unroll
        for (int k = 0; k < 8; k++) s_wi3[k][tid] = Wa[k];
    }
    u64 wh3p[16];
    {
        const u64* Wb = reinterpret_cast<const u64*>(Whh3 + tid * 32);
        #pragma unroll
        for (int k = 0; k < 16; k++) wh3p[k] = Wb[k];
    }
    float b3 = bih3[tid] + bhh3[tid];

    float c1 = 0.f, c2 = 0.f, c3 = 0.f;
    if (tid < 32) { s_h1[tid] = 0.f; s_h3[tid] = 0.f; }
    if (tid < 16) s_h2[tid] = 0.f;
    __syncthreads();

    const float* xg = g_xg + (long)b * (TSEQ * 128);
    float xa = xg[tid];
    float xb2 = xg[128 + tid];

    for (int n = 0; n < TSEQ + 2; n++) {
        int np = (n + 2 < TSEQ) ? n + 2 : TSEQ - 1;
        float xc = xg[np * 128 + tid];

        const u64* h1p = reinterpret_cast<const u64*>(s_h1);
        const u64* h2p = reinterpret_cast<const u64*>(s_h2);
        const u64* h3p = reinterpret_cast<const u64*>(s_h3);

        u64 A0 = 0ULL, A1 = 0ULL;
        #pragma unroll
        for (int k = 0; k < 16; k += 2) {
            A0 = fma2(w1p[k],     h1p[k],     A0);
            A1 = fma2(w1p[k + 1], h1p[k + 1], A1);
        }
        float g1v = xa + (lo32(A0) + hi32(A0)) + (lo32(A1) + hi32(A1));

        float g2v;
        if (tid < 64) {
            u64 B0 = 0ULL, B1 = 0ULL;
            #pragma unroll
            for (int k = 0; k < 16; k += 2) {
                B0 = fma2(w2[k],     h1p[k],     B0);
                B1 = fma2(w2[k + 1], h1p[k + 1], B1);
            }
            g2v = b2 + (lo32(B0) + hi32(B0)) + (lo32(B1) + hi32(B1));
        } else {
            u64 B0 = 0ULL;
            #pragma unroll
            for (int k = 0; k < 8; k++) B0 = fma2(w2[k], h2p[k], B0);
            g2v = lo32(B0) + hi32(B0);
        }

        u64 C0 = 0ULL, C1 = 0ULL;
        #pragma unroll
        for (int k = 0; k < 8; k++) C0 = fma2(s_wi3[k][tid], h2p[k], C0);
        #pragma unroll
        for (int k = 0; k < 16; k += 2) {
            C0 = fma2(wh3p[k],     h3p[k],     C0);
            C1 = fma2(wh3p[k + 1], h3p[k + 1], C1);
        }
        float g3v = b3 + (lo32(C0) + hi32(C0)) + (lo32(C1) + hi32(C1));

        s_g1[tid] = g1v;
        if (tid < 64) s_g2a[tid] = g2v; else s_g2b[tid - 64] = g2v;
        s_g3[tid] = g3v;
        __syncthreads();

        if (tid < 32) {
            if (n < TSEQ) {
                float gi = sigf(s_g1[tid]),      gf = sigf(s_g1[32 + tid]);
                float gg = tnh(s_g1[64 + tid]),  go = sigf(s_g1[96 + tid]);
                c1 = gf * c1 + gi * gg;
                s_h1[tid] = go * tnh(c1);
            }
        } else if (tid >= 64 && tid < 80) {
            int j = tid - 64;
            if (n >= 1 && n <= TSEQ) {
                float vi = s_g2a[j]      + s_g2b[j];
                float vf = s_g2a[16 + j] + s_g2b[16 + j];
                float vg = s_g2a[32 + j] + s_g2b[32 + j];
                float vo = s_g2a[48 + j] + s_g2b[48 + j];
                c2 = sigf(vf) * c2 + sigf(vi) * tnh(vg);
                s_h2[j] = sigf(vo) * tnh(c2);
            }
        } else if (tid >= 96) {
            int j = tid - 96;
            if (n >= 2) {
                float gi = sigf(s_g3[j]),      gf = sigf(s_g3[32 + j]);
                float gg = tnh(s_g3[64 + j]),  go = sigf(s_g3[96 + j]);
                c3 = gf * c3 + gi * gg;
                s_h3[j] = go * tnh(c3);
            }
        }
        __syncthreads();

        xa = xb2; xb2 = xc;
    }

    if (tid < 32) out[b * 32 + tid] = s_h3[tid];
}

// ---------------------------------------------------------------------------
extern "C" void kernel_launch(void* const* d_in, const int* in_sizes, int n_in,
                              void* d_out, int out_size)
{
    const float* x      = (const float*)d_in[0];
    const float* conv_w = (const float*)d_in[1];
    const float* conv_b = (const float*)d_in[2];
    const float* Wih1   = (const float*)d_in[3];
    const float* Whh1   = (const float*)d_in[4];
    const float* bih1   = (const float*)d_in[5];
    const float* bhh1   = (const float*)d_in[6];
    const float* Wih2   = (const float*)d_in[7];
    const float* Whh2   = (const float*)d_in[8];
    const float* bih2   = (const float*)d_in[9];
    const float* bhh2   = (const float*)d_in[10];
    const float* Wih3   = (const float*)d_in[11];
    const float* Whh3   = (const float*)d_in[12];
    const float* bih3   = (const float*)d_in[13];
    const float* bhh3   = (const float*)d_in[14];
    float* out = (float*)d_out;

    prep_kernel<<<(128 * 640 + 255) / 256, 256>>>(conv_w);
    conv_kernel<<<dim3((LOUT + PTILE - 1) / PTILE, NBATCH), 384>>>(x, conv_b);
    xg_kernel<<<(NBATCH * TSEQ) / 128, 256>>>(Wih1, bih1, bhh1);
    lstm_kernel<<<NBATCH, 128>>>(Whh1, Wih2, Whh2, bih2, bhh2,
                                 Wih3, Whh3, bih3, bhh3, out);
}